// round 2
// baseline (speedup 1.0000x reference)
#include <cuda_runtime.h>
#include <cstdint>
#include <cstddef>

// ---------------------------------------------------------------------------
// GCNPrediction: B=16, T=1024, FEAT=768, H=256, C=50, L=2, WIDTH=128, G=32, K=3
// Channels-last layout [B*T, C] everywhere.
// kernel_launch contains ONLY kernel launches (no runtime API) for maximal
// graph-capture safety; all scratch lives in __device__ globals referenced
// directly from device code.
// ---------------------------------------------------------------------------

#define BATCH 16
#define TLEN  1024
#define BT    (BATCH * TLEN)       // 16384
#define HCH   256
#define WCH   128
#define KNN   3
#define NCLS  50
#define BTK   (BT * KNN)           // 49152

// ------------------------- scratch (static device memory) ------------------
__device__ float g_h   [BT * HCH];                 // main activation [BT,256]
__device__ float g_t1  [BT * WCH];
__device__ float g_t2  [BT * WCH];
__device__ float g_tC  [BT * HCH];                 // t3 out; also fc_in scratch
__device__ float g_xx  [BT];
__device__ float g_dist[(size_t)BT * TLEN];        // 16M floats
__device__ int   g_idx [BT * KNN];
__device__ float g_f   [(size_t)BTK * 512];        // gathered features; also im2col scratch
__device__ float g_U   [BTK * WCH];
__device__ float g_V   [BTK * WCH];
__device__ float g_W   [BTK * HCH];

// Buffer selector so host code never needs cudaGetSymbolAddress.
#define SEL_EXT (-1)
#define SEL_H    0
#define SEL_T1   1
#define SEL_T2   2
#define SEL_TC   3
#define SEL_F    4
#define SEL_U    5
#define SEL_V    6
#define SEL_W    7

__device__ __forceinline__ float* selbuf(int s)
{
    switch (s) {
        case SEL_H:  return g_h;
        case SEL_T1: return g_t1;
        case SEL_T2: return g_t2;
        case SEL_TC: return g_tC;
        case SEL_F:  return g_f;
        case SEL_U:  return g_U;
        case SEL_V:  return g_V;
        case SEL_W:  return g_W;
    }
    return nullptr;
}

// ------------------------- generic tiled GEMM ------------------------------
// C[M,N] = act( A[M,K] (lda) @ Bw[N,K]^T (ldb) + bias[n] ), row-major.
// 64x64x16 tile, 256 threads, 4x4 register tile per thread.
__global__ __launch_bounds__(256) void gemm_kernel(
    const float* __restrict__ Aext, int Asel, int Aoff, int lda,
    const float* __restrict__ Bw, int ldb,
    float* __restrict__ Cext, int Csel, int Coff, int ldc,
    int M, int N, int K,
    const float* __restrict__ bias, int relu)
{
    const float* A = (Asel >= 0) ? (selbuf(Asel) + Aoff) : Aext;
    float*       C = (Csel >= 0) ? (selbuf(Csel) + Coff) : Cext;

    __shared__ float As[16][64];
    __shared__ float Bs[16][64];
    const int tid = threadIdx.x;
    const int m0  = blockIdx.y * 64;
    const int n0  = blockIdx.x * 64;
    const int lr  = tid >> 2;           // 0..63
    const int lq  = (tid & 3) << 2;     // 0,4,8,12
    const int ty  = tid >> 4;           // 0..15
    const int tx  = tid & 15;           // 0..15

    float acc[4][4];
#pragma unroll
    for (int i = 0; i < 4; i++)
#pragma unroll
        for (int j = 0; j < 4; j++) acc[i][j] = 0.f;

    for (int k0 = 0; k0 < K; k0 += 16) {
        float4 va = make_float4(0.f, 0.f, 0.f, 0.f);
        float4 vb = make_float4(0.f, 0.f, 0.f, 0.f);
        const int am = m0 + lr;
        if (am < M) va = *(const float4*)(A + (size_t)am * lda + k0 + lq);
        const int bn = n0 + lr;
        if (bn < N) vb = *(const float4*)(Bw + (size_t)bn * ldb + k0 + lq);
        As[lq + 0][lr] = va.x; As[lq + 1][lr] = va.y;
        As[lq + 2][lr] = va.z; As[lq + 3][lr] = va.w;
        Bs[lq + 0][lr] = vb.x; Bs[lq + 1][lr] = vb.y;
        Bs[lq + 2][lr] = vb.z; Bs[lq + 3][lr] = vb.w;
        __syncthreads();
#pragma unroll
        for (int k = 0; k < 16; k++) {
            const float4 a = *(const float4*)&As[k][ty << 2];
            const float4 b = *(const float4*)&Bs[k][tx << 2];
            acc[0][0] += a.x * b.x; acc[0][1] += a.x * b.y; acc[0][2] += a.x * b.z; acc[0][3] += a.x * b.w;
            acc[1][0] += a.y * b.x; acc[1][1] += a.y * b.y; acc[1][2] += a.y * b.z; acc[1][3] += a.y * b.w;
            acc[2][0] += a.z * b.x; acc[2][1] += a.z * b.y; acc[2][2] += a.z * b.z; acc[2][3] += a.z * b.w;
            acc[3][0] += a.w * b.x; acc[3][1] += a.w * b.y; acc[3][2] += a.w * b.z; acc[3][3] += a.w * b.w;
        }
        __syncthreads();
    }

#pragma unroll
    for (int i = 0; i < 4; i++) {
        const int m = m0 + (ty << 2) + i;
        if (m >= M) continue;
#pragma unroll
        for (int j = 0; j < 4; j++) {
            const int n = n0 + (tx << 2) + j;
            if (n >= N) continue;
            float v = acc[i][j];
            if (bias) v += bias[n];
            if (relu) v = fmaxf(v, 0.f);
            C[(size_t)m * ldc + n] = v;
        }
    }
}

// ------------------------- kNN distance GEMM -------------------------------
// D[b,t,s] = 2 * <h[b,t,:], h[b,s,:]> - xx[b,t] - xx[b,s]
__global__ __launch_bounds__(256) void dist_kernel()
{
    __shared__ float As[16][64];
    __shared__ float Bs[16][64];
    const int b   = blockIdx.z;
    const float* A = g_h + (size_t)b * TLEN * HCH;
    const float* xxb = g_xx + b * TLEN;
    const int tid = threadIdx.x;
    const int m0  = blockIdx.y * 64;
    const int n0  = blockIdx.x * 64;
    const int lr  = tid >> 2;
    const int lq  = (tid & 3) << 2;
    const int ty  = tid >> 4;
    const int tx  = tid & 15;

    float acc[4][4];
#pragma unroll
    for (int i = 0; i < 4; i++)
#pragma unroll
        for (int j = 0; j < 4; j++) acc[i][j] = 0.f;

    for (int k0 = 0; k0 < HCH; k0 += 16) {
        const float4 va = *(const float4*)(A + (size_t)(m0 + lr) * HCH + k0 + lq);
        const float4 vb = *(const float4*)(A + (size_t)(n0 + lr) * HCH + k0 + lq);
        As[lq + 0][lr] = va.x; As[lq + 1][lr] = va.y;
        As[lq + 2][lr] = va.z; As[lq + 3][lr] = va.w;
        Bs[lq + 0][lr] = vb.x; Bs[lq + 1][lr] = vb.y;
        Bs[lq + 2][lr] = vb.z; Bs[lq + 3][lr] = vb.w;
        __syncthreads();
#pragma unroll
        for (int k = 0; k < 16; k++) {
            const float4 a  = *(const float4*)&As[k][ty << 2];
            const float4 b2 = *(const float4*)&Bs[k][tx << 2];
            acc[0][0] += a.x * b2.x; acc[0][1] += a.x * b2.y; acc[0][2] += a.x * b2.z; acc[0][3] += a.x * b2.w;
            acc[1][0] += a.y * b2.x; acc[1][1] += a.y * b2.y; acc[1][2] += a.y * b2.z; acc[1][3] += a.y * b2.w;
            acc[2][0] += a.z * b2.x; acc[2][1] += a.z * b2.y; acc[2][2] += a.z * b2.z; acc[2][3] += a.z * b2.w;
            acc[3][0] += a.w * b2.x; acc[3][1] += a.w * b2.y; acc[3][2] += a.w * b2.z; acc[3][3] += a.w * b2.w;
        }
        __syncthreads();
    }

    float* Dp = g_dist + (size_t)b * TLEN * TLEN;
#pragma unroll
    for (int i = 0; i < 4; i++) {
        const int m = m0 + (ty << 2) + i;
        const float xm = xxb[m];
#pragma unroll
        for (int j = 0; j < 4; j++) {
            const int n = n0 + (tx << 2) + j;
            Dp[(size_t)m * TLEN + n] = 2.f * acc[i][j] - xm - xxb[n];
        }
    }
}

// ------------------------- squared norms -----------------------------------
__global__ __launch_bounds__(256) void xx_kernel()
{
    const int wrp  = threadIdx.x >> 5;
    const int lane = threadIdx.x & 31;
    const int row  = blockIdx.x * 8 + wrp;
    const float4* p = (const float4*)(g_h + (size_t)row * HCH);
    float s = 0.f;
    for (int c = lane; c < HCH / 4; c += 32) {
        const float4 v = p[c];
        s += v.x * v.x + v.y * v.y + v.z * v.z + v.w * v.w;
    }
    for (int o = 16; o; o >>= 1) s += __shfl_xor_sync(0xffffffffu, s, o);
    if (!lane) g_xx[row] = s;
}

// ------------------------- top-3 per row -----------------------------------
__device__ __forceinline__ bool better(float v, int i, float w, int j)
{
    return (v > w) || (v == w && i < j);   // JAX top_k tie-break: lower index
}

__global__ __launch_bounds__(256) void top3_kernel()
{
    __shared__ float sv[8][96];
    __shared__ int   si[8][96];
    const int wrp  = threadIdx.x >> 5;
    const int lane = threadIdx.x & 31;
    const int row  = blockIdx.x * 8 + wrp;
    const float* d = g_dist + (size_t)row * TLEN;

    float v0 = -3.4e38f, v1 = -3.4e38f, v2 = -3.4e38f;
    int   i0 = 0x7fffffff, i1 = 0x7fffffff, i2 = 0x7fffffff;
    for (int s = lane; s < TLEN; s += 32) {
        const float v = d[s];
        if (better(v, s, v0, i0)) { v2 = v1; i2 = i1; v1 = v0; i1 = i0; v0 = v; i0 = s; }
        else if (better(v, s, v1, i1)) { v2 = v1; i2 = i1; v1 = v; i1 = s; }
        else if (better(v, s, v2, i2)) { v2 = v; i2 = s; }
    }
    sv[wrp][lane * 3 + 0] = v0; si[wrp][lane * 3 + 0] = i0;
    sv[wrp][lane * 3 + 1] = v1; si[wrp][lane * 3 + 1] = i1;
    sv[wrp][lane * 3 + 2] = v2; si[wrp][lane * 3 + 2] = i2;
    __syncwarp();
    if (lane == 0) {
        float a0 = -3.4e38f, a1 = -3.4e38f, a2 = -3.4e38f;
        int   j0 = 0x7fffffff, j1 = 0x7fffffff, j2 = 0x7fffffff;
        for (int e = 0; e < 96; e++) {
            const float v = sv[wrp][e];
            const int   i = si[wrp][e];
            if (better(v, i, a0, j0)) { a2 = a1; j2 = j1; a1 = a0; j1 = j0; a0 = v; j0 = i; }
            else if (better(v, i, a1, j1)) { a2 = a1; j2 = j1; a1 = v; j1 = i; }
            else if (better(v, i, a2, j2)) { a2 = v; j2 = i; }
        }
        g_idx[row * 3 + 0] = j0;
        g_idx[row * 3 + 1] = j1;
        g_idx[row * 3 + 2] = j2;
    }
}

// ------------------------- gather [nbr | ctr] ------------------------------
__global__ __launch_bounds__(256) void build_f_kernel()
{
    const int gid = blockIdx.x * blockDim.x + threadIdx.x;   // BTK * 128
    if (gid >= BTK * 128) return;
    const int c4 = gid & 127;         // float4 column within 512-float row
    const int mk = gid >> 7;          // bt*3 + k
    const int bt = mk / 3;
    const int b  = bt >> 10;
    const float4* src;
    if (c4 < 64) {
        const int nb = g_idx[mk];     // neighbor t index within [0,1024)
        src = (const float4*)(g_h + (size_t)(b * TLEN + nb) * HCH) + c4;
    } else {
        src = (const float4*)(g_h + (size_t)bt * HCH) + (c4 - 64);
    }
    ((float4*)g_f)[gid] = *src;
}

// ------------------------- grouped 1x1 (s2): 4->4 per group ---------------
__global__ __launch_bounds__(256) void s2_kernel(
    const float* __restrict__ w, const float* __restrict__ bias)
{
    const int gid = blockIdx.x * blockDim.x + threadIdx.x;   // BTK * 32
    if (gid >= BTK * 32) return;
    const int g = gid & 31;
    const int m = gid >> 5;
    const float4 u = *(const float4*)(g_U + (size_t)m * WCH + g * 4);
    float4 out;
    float* op = (float*)&out;
#pragma unroll
    for (int o = 0; o < 4; o++) {
        const float4 ww = *(const float4*)(w + (g * 4 + o) * 4);
        float v = u.x * ww.x + u.y * ww.y + u.z * ww.z + u.w * ww.w + bias[g * 4 + o];
        op[o] = fmaxf(v, 0.f);
    }
    *(float4*)(g_V + (size_t)m * WCH + g * 4) = out;
}

// ------------------------- t2 grouped conv (G=32, Cin/g=4, k=3) ------------
__global__ __launch_bounds__(256) void t2conv_kernel(
    const float* __restrict__ w, const float* __restrict__ bias)
{
    const int gid = blockIdx.x * blockDim.x + threadIdx.x;   // BT * 128
    if (gid >= BT * WCH) return;
    const int c  = gid & 127;
    const int bt = gid >> 7;
    const int t  = bt & (TLEN - 1);
    const int g  = c >> 2;
    const float* wc = w + c * 12;     // [ci][kk] row for out channel c
    float acc = bias[c];
#pragma unroll
    for (int kk = 0; kk < 3; kk++) {
        const int tt = t + kk - 1;
        if (tt < 0 || tt >= TLEN) continue;
        const float4 xi = *(const float4*)(g_t1 + (size_t)(bt - t + tt) * WCH + g * 4);
        acc += xi.x * wc[0 * 3 + kk] + xi.y * wc[1 * 3 + kk]
             + xi.z * wc[2 * 3 + kk] + xi.w * wc[3 * 3 + kk];
    }
    g_t2[gid] = fmaxf(acc, 0.f);
}

// ------------------------- im2col for backbone conv (k=3) ------------------
// Col[m, ci*3+kk] = tC[b, t+kk-1, ci]  (zero pad), Col rows are 768 wide
__global__ __launch_bounds__(256) void im2col_kernel()
{
    const int gid = blockIdx.x * blockDim.x + threadIdx.x;   // BT * 256
    if (gid >= BT * HCH) return;
    const int ci = gid & 255;
    const int m  = gid >> 8;
    const int t  = m & (TLEN - 1);
    float* dst = g_f + (size_t)m * 768 + ci * 3;
#pragma unroll
    for (int kk = 0; kk < 3; kk++) {
        const int tt = t + kk - 1;
        float v = 0.f;
        if (tt >= 0 && tt < TLEN) v = g_tC[(size_t)(m - t + tt) * HCH + ci];
        dst[kk] = v;
    }
}

// ------------------------- combine: h = relu(h + tC + max_k W) -------------
__global__ __launch_bounds__(256) void combine_kernel()
{
    const int gid = blockIdx.x * blockDim.x + threadIdx.x;   // BT * 256
    if (gid >= BT * HCH) return;
    const int c = gid & 255;
    const int m = gid >> 8;
    const float* w = g_W + (size_t)m * 3 * HCH + c;
    const float mx = fmaxf(fmaxf(w[0], w[HCH]), w[2 * HCH]);
    g_h[gid] = fmaxf(g_h[gid] + g_tC[gid] + mx, 0.f);
}

// ---------------------------------------------------------------------------
extern "C" void kernel_launch(void* const* d_in, const int* in_sizes, int n_in,
                              void* d_out, int out_size)
{
    (void)in_sizes; (void)n_in; (void)out_size;
    const float* x       = (const float*)d_in[0];
    const float* fc_in_w = (const float*)d_in[1];
    const float* fc_in_b = (const float*)d_in[2];
    const float* conv_w  = (const float*)d_in[3];
    const float* conv_b  = (const float*)d_in[4];
    const float* t1_w    = (const float*)d_in[5];
    const float* t1_b    = (const float*)d_in[6];
    const float* t2_w    = (const float*)d_in[7];
    const float* t2_b    = (const float*)d_in[8];
    const float* t3_w    = (const float*)d_in[9];
    const float* t3_b    = (const float*)d_in[10];
    const float* s1_w    = (const float*)d_in[11];
    const float* s1_b    = (const float*)d_in[12];
    const float* s2_w    = (const float*)d_in[13];
    const float* s2_b    = (const float*)d_in[14];
    const float* s3_w    = (const float*)d_in[15];
    const float* s3_b    = (const float*)d_in[16];
    const float* fc_w    = (const float*)d_in[17];
    const float* fc_b    = (const float*)d_in[18];
    float* out = (float*)d_out;

    // 1) fc_in + relu : [16384,768] @ [256,768]^T -> g_tC
    gemm_kernel<<<dim3(HCH / 64, BT / 64), 256>>>(
        x, SEL_EXT, 0, 768, fc_in_w, 768,
        nullptr, SEL_TC, 0, HCH, BT, HCH, 768, fc_in_b, 1);

    // 2) backbone grouped conv (groups=4, k=3) via im2col + 4 group GEMMs
    im2col_kernel<<<BT * HCH / 256, 256>>>();
    for (int g = 0; g < 4; g++) {
        gemm_kernel<<<dim3(1, BT / 64), 256>>>(
            nullptr, SEL_F, g * 192, 768, conv_w + g * 64 * 192, 192,
            nullptr, SEL_H, g * 64, HCH, BT, 64, 192, conv_b + g * 64, 1);
    }

    // 3) GCNeXt blocks
    for (int l = 0; l < 2; l++) {
        const float* w1 = t1_w + l * WCH * HCH;  const float* b1 = t1_b + l * WCH;
        const float* w2 = t2_w + l * WCH * 12;   const float* b2 = t2_b + l * WCH;
        const float* w3 = t3_w + l * HCH * WCH;  const float* b3 = t3_b + l * HCH;
        const float* sw1 = s1_w + l * WCH * 512; const float* sb1 = s1_b + l * WCH;
        const float* sw2 = s2_w + l * WCH * 4;   const float* sb2 = s2_b + l * WCH;
        const float* sw3 = s3_w + l * HCH * WCH; const float* sb3 = s3_b + l * HCH;

        // temporal branch: t1 (1x1+relu) -> t2 (grouped k3+relu) -> t3 (1x1)
        gemm_kernel<<<dim3(WCH / 64, BT / 64), 256>>>(
            nullptr, SEL_H, 0, HCH, w1, HCH,
            nullptr, SEL_T1, 0, WCH, BT, WCH, HCH, b1, 1);
        t2conv_kernel<<<BT * WCH / 256, 256>>>(w2, b2);
        gemm_kernel<<<dim3(HCH / 64, BT / 64), 256>>>(
            nullptr, SEL_T2, 0, WCH, w3, WCH,
            nullptr, SEL_TC, 0, HCH, BT, HCH, WCH, b3, 0);

        // kNN graph
        xx_kernel<<<BT / 8, 256>>>();
        dist_kernel<<<dim3(TLEN / 64, TLEN / 64, BATCH), 256>>>();
        top3_kernel<<<BT / 8, 256>>>();

        // semantic branch
        build_f_kernel<<<(BTK * 128 + 255) / 256, 256>>>();
        gemm_kernel<<<dim3(WCH / 64, BTK / 64), 256>>>(
            nullptr, SEL_F, 0, 512, sw1, 512,
            nullptr, SEL_U, 0, WCH, BTK, WCH, 512, sb1, 1);
        s2_kernel<<<(BTK * 32 + 255) / 256, 256>>>(sw2, sb2);
        gemm_kernel<<<dim3(HCH / 64, BTK / 64), 256>>>(
            nullptr, SEL_V, 0, WCH, sw3, WCH,
            nullptr, SEL_W, 0, HCH, BTK, HCH, WCH, sb3, 0);

        // residual + max-over-k + relu (in place on g_h)
        combine_kernel<<<BT * HCH / 256, 256>>>();
    }

    // 4) final fc : [16384,256] @ [50,256]^T -> out
    gemm_kernel<<<dim3(1, BT / 64), 256>>>(
        nullptr, SEL_H, 0, HCH, fc_w, HCH,
        out, SEL_EXT, 0, NCLS, BT, NCLS, HCH, fc_b, 0);
}

// round 3
// speedup vs baseline: 1.0275x; 1.0275x over previous
#include <cuda_runtime.h>
#include <cstdint>
#include <cstddef>

// ---------------------------------------------------------------------------
// GCNPrediction: B=16, T=1024, FEAT=768, H=256, C=50, L=2, WIDTH=128, G=32, K=3
// Channels-last layout [B*T, C] everywhere.
// Round 3: 128x128x8 SGEMM tile (8x8 per-thread), z-batched conv GEMMs,
// 128-tile dist kernel. kernel_launch is launches-only.
// ---------------------------------------------------------------------------

#define BATCH 16
#define TLEN  1024
#define BT    (BATCH * TLEN)       // 16384
#define HCH   256
#define WCH   128
#define KNN   3
#define NCLS  50
#define BTK   (BT * KNN)           // 49152

// ------------------------- scratch (static device memory) ------------------
__device__ float g_h   [BT * HCH];                 // main activation [BT,256]
__device__ float g_t1  [BT * WCH];
__device__ float g_t2  [BT * WCH];
__device__ float g_tC  [BT * HCH];                 // t3 out; also fc_in scratch
__device__ float g_xx  [BT];
__device__ float g_dist[(size_t)BT * TLEN];        // 16M floats
__device__ int   g_idx [BT * KNN];
__device__ float g_f   [(size_t)BTK * 512];        // gathered features; also im2col scratch
__device__ float g_U   [BTK * WCH];
__device__ float g_V   [BTK * WCH];
__device__ float g_W   [BTK * HCH];

// Buffer selector so host code never needs cudaGetSymbolAddress.
#define SEL_EXT (-1)
#define SEL_H    0
#define SEL_T1   1
#define SEL_T2   2
#define SEL_TC   3
#define SEL_F    4
#define SEL_U    5
#define SEL_V    6
#define SEL_W    7

__device__ __forceinline__ float* selbuf(int s)
{
    switch (s) {
        case SEL_H:  return g_h;
        case SEL_T1: return g_t1;
        case SEL_T2: return g_t2;
        case SEL_TC: return g_tC;
        case SEL_F:  return g_f;
        case SEL_U:  return g_U;
        case SEL_V:  return g_V;
        case SEL_W:  return g_W;
    }
    return nullptr;
}

// ------------------------- 128x128x8 tiled GEMM ----------------------------
// C[M,N] = act( A[M,K] @ Bw[N,K]^T + bias[n] ), row-major, optional z batch:
// per z: A += Azs, Bw += Bzs, C += Czs, bias += bzs (element offsets).
// 256 threads, 8x8 register tile per thread.
__global__ __launch_bounds__(256) void gemm128_kernel(
    const float* __restrict__ Aext, int Asel, int Aoff, int lda, int Azs,
    const float* __restrict__ Bw, int ldb, int Bzs,
    float* __restrict__ Cext, int Csel, int Coff, int ldc, int Czs,
    int M, int N, int K,
    const float* __restrict__ bias, int bzs, int relu)
{
    const float* A = ((Asel >= 0) ? (selbuf(Asel) + Aoff) : Aext)
                   + (size_t)blockIdx.z * Azs;
    const float* B = Bw + (size_t)blockIdx.z * Bzs;
    float*       C = ((Csel >= 0) ? (selbuf(Csel) + Coff) : Cext)
                   + (size_t)blockIdx.z * Czs;
    const float* bb = bias ? (bias + (size_t)blockIdx.z * bzs) : nullptr;

    __shared__ float As[8][128];
    __shared__ float Bs[8][128];
    const int tid = threadIdx.x;
    const int m0  = blockIdx.y * 128;
    const int n0  = blockIdx.x * 128;
    const int lr  = tid >> 1;           // 0..127
    const int lq  = (tid & 1) << 2;     // 0 or 4
    const int ty  = tid >> 4;           // 0..15
    const int tx  = tid & 15;           // 0..15

    float acc[8][8];
#pragma unroll
    for (int i = 0; i < 8; i++)
#pragma unroll
        for (int j = 0; j < 8; j++) acc[i][j] = 0.f;

    const bool am_ok = (m0 + lr) < M;
    const bool bn_ok = (n0 + lr) < N;
    const float* aptr = A + (size_t)(m0 + lr) * lda + lq;
    const float* bptr = B + (size_t)(n0 + lr) * ldb + lq;

    for (int k0 = 0; k0 < K; k0 += 8) {
        const float4 va = am_ok ? *(const float4*)(aptr + k0)
                                : make_float4(0.f, 0.f, 0.f, 0.f);
        const float4 vb = bn_ok ? *(const float4*)(bptr + k0)
                                : make_float4(0.f, 0.f, 0.f, 0.f);
        As[lq + 0][lr] = va.x; As[lq + 1][lr] = va.y;
        As[lq + 2][lr] = va.z; As[lq + 3][lr] = va.w;
        Bs[lq + 0][lr] = vb.x; Bs[lq + 1][lr] = vb.y;
        Bs[lq + 2][lr] = vb.z; Bs[lq + 3][lr] = vb.w;
        __syncthreads();
#pragma unroll
        for (int k = 0; k < 8; k++) {
            float af[8], bf[8];
            *(float4*)&af[0] = *(const float4*)&As[k][ty << 3];
            *(float4*)&af[4] = *(const float4*)&As[k][(ty << 3) + 4];
            *(float4*)&bf[0] = *(const float4*)&Bs[k][tx << 3];
            *(float4*)&bf[4] = *(const float4*)&Bs[k][(tx << 3) + 4];
#pragma unroll
            for (int i = 0; i < 8; i++)
#pragma unroll
                for (int j = 0; j < 8; j++)
                    acc[i][j] += af[i] * bf[j];
        }
        __syncthreads();
    }

    float bj[8];
#pragma unroll
    for (int j = 0; j < 8; j++) {
        const int n = n0 + (tx << 3) + j;
        bj[j] = (bb && n < N) ? bb[n] : 0.f;
    }

    if (n0 + 128 <= N) {
#pragma unroll
        for (int i = 0; i < 8; i++) {
            const int m = m0 + (ty << 3) + i;
            if (m >= M) continue;
            float4 o0 = make_float4(acc[i][0] + bj[0], acc[i][1] + bj[1],
                                    acc[i][2] + bj[2], acc[i][3] + bj[3]);
            float4 o1 = make_float4(acc[i][4] + bj[4], acc[i][5] + bj[5],
                                    acc[i][6] + bj[6], acc[i][7] + bj[7]);
            if (relu) {
                o0.x = fmaxf(o0.x, 0.f); o0.y = fmaxf(o0.y, 0.f);
                o0.z = fmaxf(o0.z, 0.f); o0.w = fmaxf(o0.w, 0.f);
                o1.x = fmaxf(o1.x, 0.f); o1.y = fmaxf(o1.y, 0.f);
                o1.z = fmaxf(o1.z, 0.f); o1.w = fmaxf(o1.w, 0.f);
            }
            float* cp = C + (size_t)m * ldc + n0 + (tx << 3);
            *(float4*)cp       = o0;
            *(float4*)(cp + 4) = o1;
        }
    } else {
#pragma unroll
        for (int i = 0; i < 8; i++) {
            const int m = m0 + (ty << 3) + i;
            if (m >= M) continue;
#pragma unroll
            for (int j = 0; j < 8; j++) {
                const int n = n0 + (tx << 3) + j;
                if (n >= N) continue;
                float v = acc[i][j] + bj[j];
                if (relu) v = fmaxf(v, 0.f);
                C[(size_t)m * ldc + n] = v;
            }
        }
    }
}

// ------------------------- kNN distance GEMM (128 tile) --------------------
// D[b,t,s] = 2 * <h[b,t,:], h[b,s,:]> - xx[b,t] - xx[b,s]
__global__ __launch_bounds__(256) void dist128_kernel()
{
    const int b = blockIdx.z;
    const float* A   = g_h  + (size_t)b * TLEN * HCH;
    const float* xxb = g_xx + b * TLEN;

    __shared__ float As[8][128];
    __shared__ float Bs[8][128];
    const int tid = threadIdx.x;
    const int m0  = blockIdx.y * 128;
    const int n0  = blockIdx.x * 128;
    const int lr  = tid >> 1;
    const int lq  = (tid & 1) << 2;
    const int ty  = tid >> 4;
    const int tx  = tid & 15;

    float acc[8][8];
#pragma unroll
    for (int i = 0; i < 8; i++)
#pragma unroll
        for (int j = 0; j < 8; j++) acc[i][j] = 0.f;

    const float* aptr = A + (size_t)(m0 + lr) * HCH + lq;
    const float* bptr = A + (size_t)(n0 + lr) * HCH + lq;

    for (int k0 = 0; k0 < HCH; k0 += 8) {
        const float4 va = *(const float4*)(aptr + k0);
        const float4 vb = *(const float4*)(bptr + k0);
        As[lq + 0][lr] = va.x; As[lq + 1][lr] = va.y;
        As[lq + 2][lr] = va.z; As[lq + 3][lr] = va.w;
        Bs[lq + 0][lr] = vb.x; Bs[lq + 1][lr] = vb.y;
        Bs[lq + 2][lr] = vb.z; Bs[lq + 3][lr] = vb.w;
        __syncthreads();
#pragma unroll
        for (int k = 0; k < 8; k++) {
            float af[8], bf[8];
            *(float4*)&af[0] = *(const float4*)&As[k][ty << 3];
            *(float4*)&af[4] = *(const float4*)&As[k][(ty << 3) + 4];
            *(float4*)&bf[0] = *(const float4*)&Bs[k][tx << 3];
            *(float4*)&bf[4] = *(const float4*)&Bs[k][(tx << 3) + 4];
#pragma unroll
            for (int i = 0; i < 8; i++)
#pragma unroll
                for (int j = 0; j < 8; j++)
                    acc[i][j] += af[i] * bf[j];
        }
        __syncthreads();
    }

    float xn[8];
#pragma unroll
    for (int j = 0; j < 8; j++) xn[j] = xxb[n0 + (tx << 3) + j];

    float* Dp = g_dist + (size_t)b * TLEN * TLEN;
#pragma unroll
    for (int i = 0; i < 8; i++) {
        const int m = m0 + (ty << 3) + i;
        const float xm = xxb[m];
        float4 o0 = make_float4(2.f * acc[i][0] - xm - xn[0],
                                2.f * acc[i][1] - xm - xn[1],
                                2.f * acc[i][2] - xm - xn[2],
                                2.f * acc[i][3] - xm - xn[3]);
        float4 o1 = make_float4(2.f * acc[i][4] - xm - xn[4],
                                2.f * acc[i][5] - xm - xn[5],
                                2.f * acc[i][6] - xm - xn[6],
                                2.f * acc[i][7] - xm - xn[7]);
        float* dp = Dp + (size_t)m * TLEN + n0 + (tx << 3);
        *(float4*)dp       = o0;
        *(float4*)(dp + 4) = o1;
    }
}

// ------------------------- squared norms -----------------------------------
__global__ __launch_bounds__(256) void xx_kernel()
{
    const int wrp  = threadIdx.x >> 5;
    const int lane = threadIdx.x & 31;
    const int row  = blockIdx.x * 8 + wrp;
    const float4* p = (const float4*)(g_h + (size_t)row * HCH);
    float s = 0.f;
    for (int c = lane; c < HCH / 4; c += 32) {
        const float4 v = p[c];
        s += v.x * v.x + v.y * v.y + v.z * v.z + v.w * v.w;
    }
    for (int o = 16; o; o >>= 1) s += __shfl_xor_sync(0xffffffffu, s, o);
    if (!lane) g_xx[row] = s;
}

// ------------------------- top-3 per row -----------------------------------
__device__ __forceinline__ bool better(float v, int i, float w, int j)
{
    return (v > w) || (v == w && i < j);   // JAX top_k tie-break: lower index
}

__global__ __launch_bounds__(256) void top3_kernel()
{
    __shared__ float sv[8][96];
    __shared__ int   si[8][96];
    const int wrp  = threadIdx.x >> 5;
    const int lane = threadIdx.x & 31;
    const int row  = blockIdx.x * 8 + wrp;
    const float* d = g_dist + (size_t)row * TLEN;

    float v0 = -3.4e38f, v1 = -3.4e38f, v2 = -3.4e38f;
    int   i0 = 0x7fffffff, i1 = 0x7fffffff, i2 = 0x7fffffff;
    for (int s = lane; s < TLEN; s += 32) {
        const float v = d[s];
        if (better(v, s, v0, i0)) { v2 = v1; i2 = i1; v1 = v0; i1 = i0; v0 = v; i0 = s; }
        else if (better(v, s, v1, i1)) { v2 = v1; i2 = i1; v1 = v; i1 = s; }
        else if (better(v, s, v2, i2)) { v2 = v; i2 = s; }
    }
    sv[wrp][lane * 3 + 0] = v0; si[wrp][lane * 3 + 0] = i0;
    sv[wrp][lane * 3 + 1] = v1; si[wrp][lane * 3 + 1] = i1;
    sv[wrp][lane * 3 + 2] = v2; si[wrp][lane * 3 + 2] = i2;
    __syncwarp();
    if (lane == 0) {
        float a0 = -3.4e38f, a1 = -3.4e38f, a2 = -3.4e38f;
        int   j0 = 0x7fffffff, j1 = 0x7fffffff, j2 = 0x7fffffff;
        for (int e = 0; e < 96; e++) {
            const float v = sv[wrp][e];
            const int   i = si[wrp][e];
            if (better(v, i, a0, j0)) { a2 = a1; j2 = j1; a1 = a0; j1 = j0; a0 = v; j0 = i; }
            else if (better(v, i, a1, j1)) { a2 = a1; j2 = j1; a1 = v; j1 = i; }
            else if (better(v, i, a2, j2)) { a2 = v; j2 = i; }
        }
        g_idx[row * 3 + 0] = j0;
        g_idx[row * 3 + 1] = j1;
        g_idx[row * 3 + 2] = j2;
    }
}

// ------------------------- gather [nbr | ctr] ------------------------------
__global__ __launch_bounds__(256) void build_f_kernel()
{
    const int gid = blockIdx.x * blockDim.x + threadIdx.x;   // BTK * 128
    if (gid >= BTK * 128) return;
    const int c4 = gid & 127;         // float4 column within 512-float row
    const int mk = gid >> 7;          // bt*3 + k
    const int bt = mk / 3;
    const int b  = bt >> 10;
    const float4* src;
    if (c4 < 64) {
        const int nb = g_idx[mk];     // neighbor t index within [0,1024)
        src = (const float4*)(g_h + (size_t)(b * TLEN + nb) * HCH) + c4;
    } else {
        src = (const float4*)(g_h + (size_t)bt * HCH) + (c4 - 64);
    }
    ((float4*)g_f)[gid] = *src;
}

// ------------------------- grouped 1x1 (s2): 4->4 per group ---------------
__global__ __launch_bounds__(256) void s2_kernel(
    const float* __restrict__ w, const float* __restrict__ bias)
{
    const int gid = blockIdx.x * blockDim.x + threadIdx.x;   // BTK * 32
    if (gid >= BTK * 32) return;
    const int g = gid & 31;
    const int m = gid >> 5;
    const float4 u = *(const float4*)(g_U + (size_t)m * WCH + g * 4);
    float4 out;
    float* op = (float*)&out;
#pragma unroll
    for (int o = 0; o < 4; o++) {
        const float4 ww = *(const float4*)(w + (g * 4 + o) * 4);
        float v = u.x * ww.x + u.y * ww.y + u.z * ww.z + u.w * ww.w + bias[g * 4 + o];
        op[o] = fmaxf(v, 0.f);
    }
    *(float4*)(g_V + (size_t)m * WCH + g * 4) = out;
}

// ------------------------- t2 grouped conv (G=32, Cin/g=4, k=3) ------------
__global__ __launch_bounds__(256) void t2conv_kernel(
    const float* __restrict__ w, const float* __restrict__ bias)
{
    const int gid = blockIdx.x * blockDim.x + threadIdx.x;   // BT * 128
    if (gid >= BT * WCH) return;
    const int c  = gid & 127;
    const int bt = gid >> 7;
    const int t  = bt & (TLEN - 1);
    const int g  = c >> 2;
    const float* wc = w + c * 12;     // [ci][kk] row for out channel c
    float acc = bias[c];
#pragma unroll
    for (int kk = 0; kk < 3; kk++) {
        const int tt = t + kk - 1;
        if (tt < 0 || tt >= TLEN) continue;
        const float4 xi = *(const float4*)(g_t1 + (size_t)(bt - t + tt) * WCH + g * 4);
        acc += xi.x * wc[0 * 3 + kk] + xi.y * wc[1 * 3 + kk]
             + xi.z * wc[2 * 3 + kk] + xi.w * wc[3 * 3 + kk];
    }
    g_t2[gid] = fmaxf(acc, 0.f);
}

// ------------------------- im2col for backbone conv (k=3) ------------------
// Col[m, ci*3+kk] = tC[b, t+kk-1, ci]  (zero pad), Col rows are 768 wide
__global__ __launch_bounds__(256) void im2col_kernel()
{
    const int gid = blockIdx.x * blockDim.x + threadIdx.x;   // BT * 256
    if (gid >= BT * HCH) return;
    const int ci = gid & 255;
    const int m  = gid >> 8;
    const int t  = m & (TLEN - 1);
    float* dst = g_f + (size_t)m * 768 + ci * 3;
#pragma unroll
    for (int kk = 0; kk < 3; kk++) {
        const int tt = t + kk - 1;
        float v = 0.f;
        if (tt >= 0 && tt < TLEN) v = g_tC[(size_t)(m - t + tt) * HCH + ci];
        dst[kk] = v;
    }
}

// ------------------------- combine: h = relu(h + tC + max_k W) -------------
__global__ __launch_bounds__(256) void combine_kernel()
{
    const int gid = blockIdx.x * blockDim.x + threadIdx.x;   // BT * 256
    if (gid >= BT * HCH) return;
    const int c = gid & 255;
    const int m = gid >> 8;
    const float* w = g_W + (size_t)m * 3 * HCH + c;
    const float mx = fmaxf(fmaxf(w[0], w[HCH]), w[2 * HCH]);
    g_h[gid] = fmaxf(g_h[gid] + g_tC[gid] + mx, 0.f);
}

// ---------------------------------------------------------------------------
extern "C" void kernel_launch(void* const* d_in, const int* in_sizes, int n_in,
                              void* d_out, int out_size)
{
    (void)in_sizes; (void)n_in; (void)out_size;
    const float* x       = (const float*)d_in[0];
    const float* fc_in_w = (const float*)d_in[1];
    const float* fc_in_b = (const float*)d_in[2];
    const float* conv_w  = (const float*)d_in[3];
    const float* conv_b  = (const float*)d_in[4];
    const float* t1_w    = (const float*)d_in[5];
    const float* t1_b    = (const float*)d_in[6];
    const float* t2_w    = (const float*)d_in[7];
    const float* t2_b    = (const float*)d_in[8];
    const float* t3_w    = (const float*)d_in[9];
    const float* t3_b    = (const float*)d_in[10];
    const float* s1_w    = (const float*)d_in[11];
    const float* s1_b    = (const float*)d_in[12];
    const float* s2_w    = (const float*)d_in[13];
    const float* s2_b    = (const float*)d_in[14];
    const float* s3_w    = (const float*)d_in[15];
    const float* s3_b    = (const float*)d_in[16];
    const float* fc_w    = (const float*)d_in[17];
    const float* fc_b    = (const float*)d_in[18];
    float* out = (float*)d_out;

    // 1) fc_in + relu : [16384,768] @ [256,768]^T -> g_tC
    gemm128_kernel<<<dim3(2, 128), 256>>>(
        x, SEL_EXT, 0, 768, 0, fc_in_w, 768, 0,
        nullptr, SEL_TC, 0, HCH, 0, BT, HCH, 768, fc_in_b, 0, 1);

    // 2) backbone grouped conv (groups=4, k=3): im2col + one z-batched GEMM
    im2col_kernel<<<BT * HCH / 256, 256>>>();
    gemm128_kernel<<<dim3(1, 128, 4), 256>>>(
        nullptr, SEL_F, 0, 768, 192,            // A: g_f + z*192, lda 768
        conv_w, 192, 64 * 192,                  // B: conv_w + z*12288
        nullptr, SEL_H, 0, HCH, 64,             // C: g_h + z*64
        BT, 64, 192, conv_b, 64, 1);

    // 3) GCNeXt blocks
    for (int l = 0; l < 2; l++) {
        const float* w1 = t1_w + l * WCH * HCH;  const float* b1 = t1_b + l * WCH;
        const float* w2 = t2_w + l * WCH * 12;   const float* b2 = t2_b + l * WCH;
        const float* w3 = t3_w + l * HCH * WCH;  const float* b3 = t3_b + l * HCH;
        const float* sw1 = s1_w + l * WCH * 512; const float* sb1 = s1_b + l * WCH;
        const float* sw2 = s2_w + l * WCH * 4;   const float* sb2 = s2_b + l * WCH;
        const float* sw3 = s3_w + l * HCH * WCH; const float* sb3 = s3_b + l * HCH;

        // temporal branch: t1 (1x1+relu) -> t2 (grouped k3+relu) -> t3 (1x1)
        gemm128_kernel<<<dim3(1, 128), 256>>>(
            nullptr, SEL_H, 0, HCH, 0, w1, HCH, 0,
            nullptr, SEL_T1, 0, WCH, 0, BT, WCH, HCH, b1, 0, 1);
        t2conv_kernel<<<BT * WCH / 256, 256>>>(w2, b2);
        gemm128_kernel<<<dim3(2, 128), 256>>>(
            nullptr, SEL_T2, 0, WCH, 0, w3, WCH, 0,
            nullptr, SEL_TC, 0, HCH, 0, BT, HCH, WCH, b3, 0, 0);

        // kNN graph
        xx_kernel<<<BT / 8, 256>>>();
        dist128_kernel<<<dim3(8, 8, 16), 256>>>();
        top3_kernel<<<BT / 8, 256>>>();

        // semantic branch
        build_f_kernel<<<(BTK * 128 + 255) / 256, 256>>>();
        gemm128_kernel<<<dim3(1, 384), 256>>>(
            nullptr, SEL_F, 0, 512, 0, sw1, 512, 0,
            nullptr, SEL_U, 0, WCH, 0, BTK, WCH, 512, sb1, 0, 1);
        s2_kernel<<<(BTK * 32 + 255) / 256, 256>>>(sw2, sb2);
        gemm128_kernel<<<dim3(2, 384), 256>>>(
            nullptr, SEL_V, 0, WCH, 0, sw3, WCH, 0,
            nullptr, SEL_W, 0, HCH, 0, BTK, HCH, WCH, sb3, 0, 0);

        // residual + max-over-k + relu (in place on g_h)
        combine_kernel<<<BT * HCH / 256, 256>>>();
    }

    // 4) final fc : [16384,256] @ [50,256]^T -> out
    gemm128_kernel<<<dim3(1, 128), 256>>>(
        nullptr, SEL_H, 0, HCH, 0, fc_w, HCH, 0,
        out, SEL_EXT, 0, NCLS, 0, BT, NCLS, HCH, fc_b, 0, 0);
}

// round 6
// speedup vs baseline: 1.6743x; 1.6295x over previous
#include <cuda_runtime.h>
#include <cstdint>
#include <cstddef>

// ---------------------------------------------------------------------------
// GCNPrediction: B=16, T=1024, FEAT=768, H=256, C=50, L=2, WIDTH=128, G=32, K=3
// Round 6 (= audited Round 4/5 tf32 design, resubmitted after infra outage):
// tf32 mma.sync GEMM for dense layers; symmetric fp32 dist; rest as R3.
// ---------------------------------------------------------------------------

#define BATCH 16
#define TLEN  1024
#define BT    (BATCH * TLEN)       // 16384
#define HCH   256
#define WCH   128
#define KNN   3
#define NCLS  50
#define BTK   (BT * KNN)           // 49152

// ------------------------- scratch (static device memory) ------------------
__device__ float g_h   [BT * HCH];
__device__ float g_t1  [BT * WCH];
__device__ float g_t2  [BT * WCH];
__device__ float g_tC  [BT * HCH];
__device__ float g_xx  [BT];
__device__ float g_dist[(size_t)BT * TLEN];
__device__ int   g_idx [BT * KNN];
__device__ float g_f   [(size_t)BTK * 512];
__device__ float g_U   [BTK * WCH];
__device__ float g_V   [BTK * WCH];
__device__ float g_W   [BTK * HCH];

#define SEL_EXT (-1)
#define SEL_H    0
#define SEL_T1   1
#define SEL_T2   2
#define SEL_TC   3
#define SEL_F    4
#define SEL_U    5
#define SEL_V    6
#define SEL_W    7

__device__ __forceinline__ float* selbuf(int s)
{
    switch (s) {
        case SEL_H:  return g_h;
        case SEL_T1: return g_t1;
        case SEL_T2: return g_t2;
        case SEL_TC: return g_tC;
        case SEL_F:  return g_f;
        case SEL_U:  return g_U;
        case SEL_V:  return g_V;
        case SEL_W:  return g_W;
    }
    return nullptr;
}

__device__ __forceinline__ unsigned f2tf32(float x)
{
    unsigned r;
    asm("cvt.rna.tf32.f32 %0, %1;" : "=r"(r) : "f"(x));
    return r;
}

__device__ __forceinline__ void mma_tf32(
    float& c0, float& c1, float& c2, float& c3,
    unsigned a0, unsigned a1, unsigned a2, unsigned a3,
    unsigned b0, unsigned b1)
{
    asm volatile(
        "mma.sync.aligned.m16n8k8.row.col.f32.tf32.tf32.f32 "
        "{%0,%1,%2,%3}, {%4,%5,%6,%7}, {%8,%9}, {%0,%1,%2,%3};"
        : "+f"(c0), "+f"(c1), "+f"(c2), "+f"(c3)
        : "r"(a0), "r"(a1), "r"(a2), "r"(a3), "r"(b0), "r"(b1));
}

// ------------------------- tf32 tensor-core GEMM ---------------------------
// C[M,N] = act( A[M,K] @ Bw[N,K]^T + bias[n] ), row-major; optional z batch.
// 128x128x16 tile, 256 threads (8 warps of 64x32), double-buffered smem.
// Requires: M % 128 == 0, K % 16 == 0, N even.
#define TFPAD 136
__global__ __launch_bounds__(256, 2) void gemm_tf32_kernel(
    const float* __restrict__ Aext, int Asel, int Aoff, int lda, int Azs,
    const float* __restrict__ Bw, int ldb, int Bzs,
    float* __restrict__ Cext, int Csel, int Coff, int ldc, int Czs,
    int M, int N, int K,
    const float* __restrict__ bias, int bzs, int relu)
{
    const float* A = ((Asel >= 0) ? (selbuf(Asel) + Aoff) : Aext)
                   + (size_t)blockIdx.z * Azs;
    const float* B = Bw + (size_t)blockIdx.z * Bzs;
    float*       C = ((Csel >= 0) ? (selbuf(Csel) + Coff) : Cext)
                   + (size_t)blockIdx.z * Czs;
    const float* bb = bias ? (bias + (size_t)blockIdx.z * bzs) : nullptr;

    __shared__ unsigned As[2][16][TFPAD];
    __shared__ unsigned Bs[2][16][TFPAD];

    const int tid  = threadIdx.x;
    const int lane = tid & 31;
    const int w    = tid >> 5;       // 0..7
    const int wm   = w & 1;          // 0..1  (64-row half)
    const int wn   = w >> 1;         // 0..3  (32-col quarter)
    const int g    = lane >> 2;      // 0..7
    const int tig  = lane & 3;       // 0..3
    const int m0   = blockIdx.y * 128;
    const int n0   = blockIdx.x * 128;

    // loader mapping: row = tid & 63 (and +64), float4-quad = tid >> 6
    const int lm = tid & 63;
    const int lf = tid >> 6;                      // 0..3
    const float* arow = A + (size_t)(m0 + lm) * lda + (lf << 2);
    const float* brow = B + (size_t)(n0 + lm) * ldb + (lf << 2);
    const bool bok0 = (n0 + lm)      < N;
    const bool bok1 = (n0 + lm + 64) < N;

    float acc[4][4][4];
#pragma unroll
    for (int i = 0; i < 4; i++)
#pragma unroll
        for (int j = 0; j < 4; j++)
#pragma unroll
            for (int q = 0; q < 4; q++) acc[i][j][q] = 0.f;

    const int nk = K / 16;
    const float4 z4 = make_float4(0.f, 0.f, 0.f, 0.f);

    float4 ra0 = *(const float4*)(arow);
    float4 ra1 = *(const float4*)(arow + (size_t)64 * lda);
    float4 rb0 = bok0 ? *(const float4*)(brow) : z4;
    float4 rb1 = bok1 ? *(const float4*)(brow + (size_t)64 * ldb) : z4;

    for (int kt = 0; kt < nk; kt++) {
        const int buf = kt & 1;
        // store staged regs (tf32-converted) into smem
        {
            const int kb = lf << 2;
            As[buf][kb + 0][lm] = f2tf32(ra0.x);
            As[buf][kb + 1][lm] = f2tf32(ra0.y);
            As[buf][kb + 2][lm] = f2tf32(ra0.z);
            As[buf][kb + 3][lm] = f2tf32(ra0.w);
            As[buf][kb + 0][lm + 64] = f2tf32(ra1.x);
            As[buf][kb + 1][lm + 64] = f2tf32(ra1.y);
            As[buf][kb + 2][lm + 64] = f2tf32(ra1.z);
            As[buf][kb + 3][lm + 64] = f2tf32(ra1.w);
            Bs[buf][kb + 0][lm] = f2tf32(rb0.x);
            Bs[buf][kb + 1][lm] = f2tf32(rb0.y);
            Bs[buf][kb + 2][lm] = f2tf32(rb0.z);
            Bs[buf][kb + 3][lm] = f2tf32(rb0.w);
            Bs[buf][kb + 0][lm + 64] = f2tf32(rb1.x);
            Bs[buf][kb + 1][lm + 64] = f2tf32(rb1.y);
            Bs[buf][kb + 2][lm + 64] = f2tf32(rb1.z);
            Bs[buf][kb + 3][lm + 64] = f2tf32(rb1.w);
        }
        __syncthreads();

        if (kt + 1 < nk) {
            const int k0 = (kt + 1) * 16;
            ra0 = *(const float4*)(arow + k0);
            ra1 = *(const float4*)(arow + (size_t)64 * lda + k0);
            rb0 = bok0 ? *(const float4*)(brow + k0) : z4;
            rb1 = bok1 ? *(const float4*)(brow + (size_t)64 * ldb + k0) : z4;
        }

#pragma unroll
        for (int kk = 0; kk < 16; kk += 8) {
            unsigned a[4][4], b[4][2];
            const unsigned* Ak = &As[buf][kk][0];
            const unsigned* Bk = &Bs[buf][kk][0];
#pragma unroll
            for (int i = 0; i < 4; i++) {
                const int mb = wm * 64 + i * 16 + g;
                a[i][0] = Ak[(size_t)tig * TFPAD + mb];
                a[i][1] = Ak[(size_t)tig * TFPAD + mb + 8];
                a[i][2] = Ak[(size_t)(tig + 4) * TFPAD + mb];
                a[i][3] = Ak[(size_t)(tig + 4) * TFPAD + mb + 8];
            }
#pragma unroll
            for (int j = 0; j < 4; j++) {
                const int nb = wn * 32 + j * 8 + g;
                b[j][0] = Bk[(size_t)tig * TFPAD + nb];
                b[j][1] = Bk[(size_t)(tig + 4) * TFPAD + nb];
            }
#pragma unroll
            for (int i = 0; i < 4; i++)
#pragma unroll
                for (int j = 0; j < 4; j++)
                    mma_tf32(acc[i][j][0], acc[i][j][1], acc[i][j][2], acc[i][j][3],
                             a[i][0], a[i][1], a[i][2], a[i][3],
                             b[j][0], b[j][1]);
        }
        __syncthreads();
    }

    // epilogue
    float bv[4][2];
#pragma unroll
    for (int j = 0; j < 4; j++) {
        const int col = n0 + wn * 32 + j * 8 + tig * 2;
        const bool ok = bb && (col < N);
        bv[j][0] = ok ? bb[col] : 0.f;
        bv[j][1] = ok ? bb[col + 1] : 0.f;
    }
#pragma unroll
    for (int i = 0; i < 4; i++) {
        const int row = m0 + wm * 64 + i * 16 + g;
#pragma unroll
        for (int j = 0; j < 4; j++) {
            const int col = n0 + wn * 32 + j * 8 + tig * 2;
            if (col >= N) continue;
            float2 lo = make_float2(acc[i][j][0] + bv[j][0],
                                    acc[i][j][1] + bv[j][1]);
            float2 hi = make_float2(acc[i][j][2] + bv[j][0],
                                    acc[i][j][3] + bv[j][1]);
            if (relu) {
                lo.x = fmaxf(lo.x, 0.f); lo.y = fmaxf(lo.y, 0.f);
                hi.x = fmaxf(hi.x, 0.f); hi.y = fmaxf(hi.y, 0.f);
            }
            *(float2*)(C + (size_t)row * ldc + col)       = lo;
            *(float2*)(C + (size_t)(row + 8) * ldc + col) = hi;
        }
    }
}

// ------------------------- fp32 128x128 tile GEMM (final fc only) ----------
__global__ __launch_bounds__(256) void gemm128_kernel(
    const float* __restrict__ Aext, int Asel, int Aoff, int lda,
    const float* __restrict__ Bw, int ldb,
    float* __restrict__ Cext, int Csel, int Coff, int ldc,
    int M, int N, int K,
    const float* __restrict__ bias, int relu)
{
    const float* A = (Asel >= 0) ? (selbuf(Asel) + Aoff) : Aext;
    const float* B = Bw;
    float*       C = (Csel >= 0) ? (selbuf(Csel) + Coff) : Cext;

    __shared__ float As[8][128];
    __shared__ float Bs[8][128];
    const int tid = threadIdx.x;
    const int m0  = blockIdx.y * 128;
    const int n0  = blockIdx.x * 128;
    const int lr  = tid >> 1;
    const int lq  = (tid & 1) << 2;
    const int ty  = tid >> 4;
    const int tx  = tid & 15;

    float acc[8][8];
#pragma unroll
    for (int i = 0; i < 8; i++)
#pragma unroll
        for (int j = 0; j < 8; j++) acc[i][j] = 0.f;

    const bool am_ok = (m0 + lr) < M;
    const bool bn_ok = (n0 + lr) < N;
    const float* aptr = A + (size_t)(m0 + lr) * lda + lq;
    const float* bptr = B + (size_t)(n0 + lr) * ldb + lq;

    for (int k0 = 0; k0 < K; k0 += 8) {
        const float4 va = am_ok ? *(const float4*)(aptr + k0)
                                : make_float4(0.f, 0.f, 0.f, 0.f);
        const float4 vb = bn_ok ? *(const float4*)(bptr + k0)
                                : make_float4(0.f, 0.f, 0.f, 0.f);
        As[lq + 0][lr] = va.x; As[lq + 1][lr] = va.y;
        As[lq + 2][lr] = va.z; As[lq + 3][lr] = va.w;
        Bs[lq + 0][lr] = vb.x; Bs[lq + 1][lr] = vb.y;
        Bs[lq + 2][lr] = vb.z; Bs[lq + 3][lr] = vb.w;
        __syncthreads();
#pragma unroll
        for (int k = 0; k < 8; k++) {
            float af[8], bf[8];
            *(float4*)&af[0] = *(const float4*)&As[k][ty << 3];
            *(float4*)&af[4] = *(const float4*)&As[k][(ty << 3) + 4];
            *(float4*)&bf[0] = *(const float4*)&Bs[k][tx << 3];
            *(float4*)&bf[4] = *(const float4*)&Bs[k][(tx << 3) + 4];
#pragma unroll
            for (int i = 0; i < 8; i++)
#pragma unroll
                for (int j = 0; j < 8; j++)
                    acc[i][j] += af[i] * bf[j];
        }
        __syncthreads();
    }

#pragma unroll
    for (int i = 0; i < 8; i++) {
        const int m = m0 + (ty << 3) + i;
        if (m >= M) continue;
#pragma unroll
        for (int j = 0; j < 8; j++) {
            const int n = n0 + (tx << 3) + j;
            if (n >= N) continue;
            float v = acc[i][j];
            if (bias) v += bias[n];
            if (relu) v = fmaxf(v, 0.f);
            C[(size_t)m * ldc + n] = v;
        }
    }
}

// ------------------------- kNN distance GEMM (symmetric, fp32) -------------
// D[b,t,s] = 2 * <h[b,t,:], h[b,s,:]> - xx[b,t] - xx[b,s]
// Only upper-triangle 128x128 blocks computed; transpose written for off-diag.
__global__ __launch_bounds__(256) void dist128_kernel()
{
    const int b = blockIdx.z;
    const float* A   = g_h  + (size_t)b * TLEN * HCH;
    const float* xxb = g_xx + b * TLEN;

    // map linear pair index -> (bi, bj), bj >= bi, 8x8 blocks
    int p = blockIdx.x, bi = 0;
    while (p >= 8 - bi) { p -= 8 - bi; bi++; }
    const int bj = bi + p;
    const int m0 = bi * 128;
    const int n0 = bj * 128;

    __shared__ float As[8][128];
    __shared__ float Bs[8][128];
    const int tid = threadIdx.x;
    const int lr  = tid >> 1;
    const int lq  = (tid & 1) << 2;
    const int ty  = tid >> 4;
    const int tx  = tid & 15;

    float acc[8][8];
#pragma unroll
    for (int i = 0; i < 8; i++)
#pragma unroll
        for (int j = 0; j < 8; j++) acc[i][j] = 0.f;

    const float* aptr = A + (size_t)(m0 + lr) * HCH + lq;
    const float* bptr = A + (size_t)(n0 + lr) * HCH + lq;

    for (int k0 = 0; k0 < HCH; k0 += 8) {
        const float4 va = *(const float4*)(aptr + k0);
        const float4 vb = *(const float4*)(bptr + k0);
        As[lq + 0][lr] = va.x; As[lq + 1][lr] = va.y;
        As[lq + 2][lr] = va.z; As[lq + 3][lr] = va.w;
        Bs[lq + 0][lr] = vb.x; Bs[lq + 1][lr] = vb.y;
        Bs[lq + 2][lr] = vb.z; Bs[lq + 3][lr] = vb.w;
        __syncthreads();
#pragma unroll
        for (int k = 0; k < 8; k++) {
            float af[8], bf[8];
            *(float4*)&af[0] = *(const float4*)&As[k][ty << 3];
            *(float4*)&af[4] = *(const float4*)&As[k][(ty << 3) + 4];
            *(float4*)&bf[0] = *(const float4*)&Bs[k][tx << 3];
            *(float4*)&bf[4] = *(const float4*)&Bs[k][(tx << 3) + 4];
#pragma unroll
            for (int i = 0; i < 8; i++)
#pragma unroll
                for (int j = 0; j < 8; j++)
                    acc[i][j] += af[i] * bf[j];
        }
        __syncthreads();
    }

    float xn[8];
#pragma unroll
    for (int j = 0; j < 8; j++) xn[j] = xxb[n0 + (tx << 3) + j];

    float* Dp = g_dist + (size_t)b * TLEN * TLEN;
    // finalize values in-place
#pragma unroll
    for (int i = 0; i < 8; i++) {
        const float xm = xxb[m0 + (ty << 3) + i];
#pragma unroll
        for (int j = 0; j < 8; j++)
            acc[i][j] = 2.f * acc[i][j] - xm - xn[j];
    }
    // forward write
#pragma unroll
    for (int i = 0; i < 8; i++) {
        float* dp = Dp + (size_t)(m0 + (ty << 3) + i) * TLEN + n0 + (tx << 3);
        *(float4*)dp       = make_float4(acc[i][0], acc[i][1], acc[i][2], acc[i][3]);
        *(float4*)(dp + 4) = make_float4(acc[i][4], acc[i][5], acc[i][6], acc[i][7]);
    }
    // transposed write for off-diagonal blocks
    if (bi != bj) {
#pragma unroll
        for (int j = 0; j < 8; j++) {
            float* dp = Dp + (size_t)(n0 + (tx << 3) + j) * TLEN + m0 + (ty << 3);
            *(float4*)dp       = make_float4(acc[0][j], acc[1][j], acc[2][j], acc[3][j]);
            *(float4*)(dp + 4) = make_float4(acc[4][j], acc[5][j], acc[6][j], acc[7][j]);
        }
    }
}

// ------------------------- squared norms -----------------------------------
__global__ __launch_bounds__(256) void xx_kernel()
{
    const int wrp  = threadIdx.x >> 5;
    const int lane = threadIdx.x & 31;
    const int row  = blockIdx.x * 8 + wrp;
    const float4* p = (const float4*)(g_h + (size_t)row * HCH);
    float s = 0.f;
    for (int c = lane; c < HCH / 4; c += 32) {
        const float4 v = p[c];
        s += v.x * v.x + v.y * v.y + v.z * v.z + v.w * v.w;
    }
    for (int o = 16; o; o >>= 1) s += __shfl_xor_sync(0xffffffffu, s, o);
    if (!lane) g_xx[row] = s;
}

// ------------------------- top-3 per row -----------------------------------
__device__ __forceinline__ bool better(float v, int i, float w, int j)
{
    return (v > w) || (v == w && i < j);
}

__global__ __launch_bounds__(256) void top3_kernel()
{
    __shared__ float sv[8][96];
    __shared__ int   si[8][96];
    const int wrp  = threadIdx.x >> 5;
    const int lane = threadIdx.x & 31;
    const int row  = blockIdx.x * 8 + wrp;
    const float* d = g_dist + (size_t)row * TLEN;

    float v0 = -3.4e38f, v1 = -3.4e38f, v2 = -3.4e38f;
    int   i0 = 0x7fffffff, i1 = 0x7fffffff, i2 = 0x7fffffff;
    for (int s = lane; s < TLEN; s += 32) {
        const float v = d[s];
        if (better(v, s, v0, i0)) { v2 = v1; i2 = i1; v1 = v0; i1 = i0; v0 = v; i0 = s; }
        else if (better(v, s, v1, i1)) { v2 = v1; i2 = i1; v1 = v; i1 = s; }
        else if (better(v, s, v2, i2)) { v2 = v; i2 = s; }
    }
    sv[wrp][lane * 3 + 0] = v0; si[wrp][lane * 3 + 0] = i0;
    sv[wrp][lane * 3 + 1] = v1; si[wrp][lane * 3 + 1] = i1;
    sv[wrp][lane * 3 + 2] = v2; si[wrp][lane * 3 + 2] = i2;
    __syncwarp();
    if (lane == 0) {
        float a0 = -3.4e38f, a1 = -3.4e38f, a2 = -3.4e38f;
        int   j0 = 0x7fffffff, j1 = 0x7fffffff, j2 = 0x7fffffff;
        for (int e = 0; e < 96; e++) {
            const float v = sv[wrp][e];
            const int   i = si[wrp][e];
            if (better(v, i, a0, j0)) { a2 = a1; j2 = j1; a1 = a0; j1 = j0; a0 = v; j0 = i; }
            else if (better(v, i, a1, j1)) { a2 = a1; j2 = j1; a1 = v; j1 = i; }
            else if (better(v, i, a2, j2)) { a2 = v; j2 = i; }
        }
        g_idx[row * 3 + 0] = j0;
        g_idx[row * 3 + 1] = j1;
        g_idx[row * 3 + 2] = j2;
    }
}

// ------------------------- gather [nbr | ctr] ------------------------------
__global__ __launch_bounds__(256) void build_f_kernel()
{
    const int gid = blockIdx.x * blockDim.x + threadIdx.x;
    if (gid >= BTK * 128) return;
    const int c4 = gid & 127;
    const int mk = gid >> 7;
    const int bt = mk / 3;
    const int b  = bt >> 10;
    const float4* src;
    if (c4 < 64) {
        const int nb = g_idx[mk];
        src = (const float4*)(g_h + (size_t)(b * TLEN + nb) * HCH) + c4;
    } else {
        src = (const float4*)(g_h + (size_t)bt * HCH) + (c4 - 64);
    }
    ((float4*)g_f)[gid] = *src;
}

// ------------------------- grouped 1x1 (s2) --------------------------------
__global__ __launch_bounds__(256) void s2_kernel(
    const float* __restrict__ w, const float* __restrict__ bias)
{
    const int gid = blockIdx.x * blockDim.x + threadIdx.x;
    if (gid >= BTK * 32) return;
    const int g = gid & 31;
    const int m = gid >> 5;
    const float4 u = *(const float4*)(g_U + (size_t)m * WCH + g * 4);
    float4 out;
    float* op = (float*)&out;
#pragma unroll
    for (int o = 0; o < 4; o++) {
        const float4 ww = *(const float4*)(w + (g * 4 + o) * 4);
        float v = u.x * ww.x + u.y * ww.y + u.z * ww.z + u.w * ww.w + bias[g * 4 + o];
        op[o] = fmaxf(v, 0.f);
    }
    *(float4*)(g_V + (size_t)m * WCH + g * 4) = out;
}

// ------------------------- t2 grouped conv ---------------------------------
__global__ __launch_bounds__(256) void t2conv_kernel(
    const float* __restrict__ w, const float* __restrict__ bias)
{
    const int gid = blockIdx.x * blockDim.x + threadIdx.x;
    if (gid >= BT * WCH) return;
    const int c  = gid & 127;
    const int bt = gid >> 7;
    const int t  = bt & (TLEN - 1);
    const int g  = c >> 2;
    const float* wc = w + c * 12;
    float acc = bias[c];
#pragma unroll
    for (int kk = 0; kk < 3; kk++) {
        const int tt = t + kk - 1;
        if (tt < 0 || tt >= TLEN) continue;
        const float4 xi = *(const float4*)(g_t1 + (size_t)(bt - t + tt) * WCH + g * 4);
        acc += xi.x * wc[0 * 3 + kk] + xi.y * wc[1 * 3 + kk]
             + xi.z * wc[2 * 3 + kk] + xi.w * wc[3 * 3 + kk];
    }
    g_t2[gid] = fmaxf(acc, 0.f);
}

// ------------------------- im2col for backbone conv ------------------------
__global__ __launch_bounds__(256) void im2col_kernel()
{
    const int gid = blockIdx.x * blockDim.x + threadIdx.x;
    if (gid >= BT * HCH) return;
    const int ci = gid & 255;
    const int m  = gid >> 8;
    const int t  = m & (TLEN - 1);
    float* dst = g_f + (size_t)m * 768 + ci * 3;
#pragma unroll
    for (int kk = 0; kk < 3; kk++) {
        const int tt = t + kk - 1;
        float v = 0.f;
        if (tt >= 0 && tt < TLEN) v = g_tC[(size_t)(m - t + tt) * HCH + ci];
        dst[kk] = v;
    }
}

// ------------------------- combine -----------------------------------------
__global__ __launch_bounds__(256) void combine_kernel()
{
    const int gid = blockIdx.x * blockDim.x + threadIdx.x;
    if (gid >= BT * HCH) return;
    const int c = gid & 255;
    const int m = gid >> 8;
    const float* w = g_W + (size_t)m * 3 * HCH + c;
    const float mx = fmaxf(fmaxf(w[0], w[HCH]), w[2 * HCH]);
    g_h[gid] = fmaxf(g_h[gid] + g_tC[gid] + mx, 0.f);
}

// ---------------------------------------------------------------------------
extern "C" void kernel_launch(void* const* d_in, const int* in_sizes, int n_in,
                              void* d_out, int out_size)
{
    (void)in_sizes; (void)n_in; (void)out_size;
    const float* x       = (const float*)d_in[0];
    const float* fc_in_w = (const float*)d_in[1];
    const float* fc_in_b = (const float*)d_in[2];
    const float* conv_w  = (const float*)d_in[3];
    const float* conv_b  = (const float*)d_in[4];
    const float* t1_w    = (const float*)d_in[5];
    const float* t1_b    = (const float*)d_in[6];
    const float* t2_w    = (const float*)d_in[7];
    const float* t2_b    = (const float*)d_in[8];
    const float* t3_w    = (const float*)d_in[9];
    const float* t3_b    = (const float*)d_in[10];
    const float* s1_w    = (const float*)d_in[11];
    const float* s1_b    = (const float*)d_in[12];
    const float* s2_w    = (const float*)d_in[13];
    const float* s2_b    = (const float*)d_in[14];
    const float* s3_w    = (const float*)d_in[15];
    const float* s3_b    = (const float*)d_in[16];
    const float* fc_w    = (const float*)d_in[17];
    const float* fc_b    = (const float*)d_in[18];
    float* out = (float*)d_out;

    // 1) fc_in + relu : [16384,768] @ [256,768]^T -> g_tC   (tf32)
    gemm_tf32_kernel<<<dim3(2, 128), 256>>>(
        x, SEL_EXT, 0, 768, 0, fc_in_w, 768, 0,
        nullptr, SEL_TC, 0, HCH, 0, BT, HCH, 768, fc_in_b, 0, 1);

    // 2) backbone grouped conv: im2col + z-batched tf32 GEMM (N=64, K=192)
    im2col_kernel<<<BT * HCH / 256, 256>>>();
    gemm_tf32_kernel<<<dim3(1, 128, 4), 256>>>(
        nullptr, SEL_F, 0, 768, 192,
        conv_w, 192, 64 * 192,
        nullptr, SEL_H, 0, HCH, 64,
        BT, 64, 192, conv_b, 64, 1);

    // 3) GCNeXt blocks
    for (int l = 0; l < 2; l++) {
        const float* w1 = t1_w + l * WCH * HCH;  const float* b1 = t1_b + l * WCH;
        const float* w2 = t2_w + l * WCH * 12;   const float* b2 = t2_b + l * WCH;
        const float* w3 = t3_w + l * HCH * WCH;  const float* b3 = t3_b + l * HCH;
        const float* sw1 = s1_w + l * WCH * 512; const float* sb1 = s1_b + l * WCH;
        const float* sw2 = s2_w + l * WCH * 4;   const float* sb2 = s2_b + l * WCH;
        const float* sw3 = s3_w + l * HCH * WCH; const float* sb3 = s3_b + l * HCH;

        // temporal branch
        gemm_tf32_kernel<<<dim3(1, 128), 256>>>(
            nullptr, SEL_H, 0, HCH, 0, w1, HCH, 0,
            nullptr, SEL_T1, 0, WCH, 0, BT, WCH, HCH, b1, 0, 1);
        t2conv_kernel<<<BT * WCH / 256, 256>>>(w2, b2);
        gemm_tf32_kernel<<<dim3(2, 128), 256>>>(
            nullptr, SEL_T2, 0, WCH, 0, w3, WCH, 0,
            nullptr, SEL_TC, 0, HCH, 0, BT, HCH, WCH, b3, 0, 0);

        // kNN graph (fp32, symmetric blocks)
        xx_kernel<<<BT / 8, 256>>>();
        dist128_kernel<<<dim3(36, 1, 16), 256>>>();
        top3_kernel<<<BT / 8, 256>>>();

        // semantic branch
        build_f_kernel<<<(BTK * 128 + 255) / 256, 256>>>();
        gemm_tf32_kernel<<<dim3(1, 384), 256>>>(
            nullptr, SEL_F, 0, 512, 0, sw1, 512, 0,
            nullptr, SEL_U, 0, WCH, 0, BTK, WCH, 512, sb1, 0, 1);
        s2_kernel<<<(BTK * 32 + 255) / 256, 256>>>(sw2, sb2);
        gemm_tf32_kernel<<<dim3(2, 384), 256>>>(
            nullptr, SEL_V, 0, WCH, 0, sw3, WCH, 0,
            nullptr, SEL_W, 0, HCH, 0, BTK, HCH, WCH, sb3, 0, 0);

        // residual + max-over-k + relu
        combine_kernel<<<BT * HCH / 256, 256>>>();
    }

    // 4) final fc : [16384,256] @ [50,256]^T -> out   (fp32)
    gemm128_kernel<<<dim3(1, 128), 256>>>(
        nullptr, SEL_H, 0, HCH, fc_w, HCH,
        out, SEL_EXT, 0, NCLS, BT, NCLS, HCH, fc_b, 0);
}